// round 12
// baseline (speedup 1.0000x reference)
#include <cuda_runtime.h>
#include <cuda_bf16.h>
#include <math.h>

// Problem constants
#define VOCAB 50000
#define D_EMB 256
#define H_DIM 512
#define B_SZ  64
#define T_LEN 512
#define KTOT  (D_EMB + H_DIM)   // 768
#define G4H   (4 * H_DIM)       // 2048

// Persistent-kernel config
#define NCTA 128                // CTA owns 4 h-cols -> 16 gate cols
#define NTHR 512                // 16 warps = 8 k-groups x 2 batch-halves
#define HC   4
#define XK_PER 32               // x k's per k-group (256/8)
#define HK_PER 64               // h k's per k-group (512/8)

// SMEM: reduction buffer only -> weights live in L1 via LDG
#define RED_F (16 * 16 * 32)    // 8192 floats = 32KB

typedef unsigned long long u64;

// -------- device scratch (allocation-free rule: __device__ globals) --------
__device__ float    g_XT[T_LEN * D_EMB * B_SZ];       // [t][d][b]
__device__ float    g_hbuf[2][H_DIM * B_SZ];          // [h][b] double buffer
__device__ float2   g_Wdup[KTOT][NCTA][16];           // {w,w} pairs, [k][cta][c], c=g*4+cl
__device__ unsigned g_bar_count;
__device__ unsigned g_bar_gen;

__device__ __forceinline__ u64 fma2(u64 a, u64 b, u64 c) {
    u64 d; asm("fma.rn.f32x2 %0, %1, %2, %3;" : "=l"(d) : "l"(a), "l"(b), "l"(c)); return d;
}
__device__ __forceinline__ float sigf(float x) { return 1.0f / (1.0f + __expf(-x)); }

// ============================================================================
// Kernel 1a: embedding gather + transpose; zero h0; reset barrier state.
// ============================================================================
__global__ void gather_transpose_kernel(const int* __restrict__ wi,
                                        const float* __restrict__ emb) {
    int t   = blockIdx.x;
    int tid = threadIdx.x;
    int b   = tid & 63;
    int q   = tid >> 6;

    int row = wi[b * T_LEN + t];
    const float* er = emb + (size_t)row * D_EMB + q * 64;
    float* xo = g_XT + (size_t)t * D_EMB * B_SZ;

#pragma unroll
    for (int i = 0; i < 64; i += 4) {
        float4 v = __ldg((const float4*)(er + i));
        int d = q * 64 + i;
        xo[(d + 0) * B_SZ + b] = v.x;
        xo[(d + 1) * B_SZ + b] = v.y;
        xo[(d + 2) * B_SZ + b] = v.z;
        xo[(d + 3) * B_SZ + b] = v.w;
    }
    if (tid < B_SZ) g_hbuf[0][t * B_SZ + tid] = 0.0f;   // block t owns h-row t
    if (t == 0 && tid == 0) { g_bar_gen = 0; g_bar_count = 0; }
}

// ============================================================================
// Kernel 1b: pack weights into per-CTA contiguous duplicated pairs.
// g_Wdup[k][cta][c] = {w,w}, w = kern[k][ (c>>2)*H + cta*4 + (c&3) ].
// Each CTA's per-k block is 128B = exactly one cache line.
// ============================================================================
__global__ void pack_weights_kernel(const float* __restrict__ kern) {
    int k   = blockIdx.x;       // 0..767
    int tid = threadIdx.x;      // 256
    const float* kr = kern + (size_t)k * G4H;
    for (int e = tid; e < NCTA * 16; e += 256) {
        int cta = e >> 4, c = e & 15;
        float v = kr[(c >> 2) * H_DIM + cta * 4 + (c & 3)];
        g_Wdup[k][cta][c] = make_float2(v, v);
    }
}

// ============================================================================
// Kernel 2: persistent LSTM, 128 CTAs x 512 threads.
//  - warp w = (kg = w>>1, bh = w&1): k-octant, batch-half
//  - lane (bg = lane>>2, cg = lane&3): 4 batches x 4 cols, acc[2][4] f32x2
//  - acts:    __ldcg LDG.128 (1 line/warp, L2-served, bypasses L1)
//  - weights: plain LDG.128 from g_Wdup (1 line/warp, L1-RESIDENT across steps)
//  - x-GEMM for step t+1 overlapped with the grid barrier wait
// ============================================================================

// per-k inner body: 3 LDG + 8 FFMA2, zero MOVs
#define KBODY(AP, WP)                                               \
    {                                                               \
        ulonglong2 va = __ldcg((const ulonglong2*)(AP));            \
        ulonglong2 wA = __ldg((const ulonglong2*)(WP));             \
        ulonglong2 wB = __ldg((const ulonglong2*)(WP) + 1);         \
        acc[0][0] = fma2(va.x, wA.x, acc[0][0]);                    \
        acc[0][1] = fma2(va.x, wA.y, acc[0][1]);                    \
        acc[0][2] = fma2(va.x, wB.x, acc[0][2]);                    \
        acc[0][3] = fma2(va.x, wB.y, acc[0][3]);                    \
        acc[1][0] = fma2(va.y, wA.x, acc[1][0]);                    \
        acc[1][1] = fma2(va.y, wA.y, acc[1][1]);                    \
        acc[1][2] = fma2(va.y, wB.x, acc[1][2]);                    \
        acc[1][3] = fma2(va.y, wB.y, acc[1][3]);                    \
    }

#define WK_STRIDE (NCTA * 16)   // float2 elements per k row

__global__ void __launch_bounds__(NTHR, 1)
lstm_persistent_kernel(const float* __restrict__ bias,
                       const int*   __restrict__ num_words,
                       float*       __restrict__ out) {
    __shared__ float red[RED_F];    // [w][e][lane]

    const int tid  = threadIdx.x;
    const int w    = tid >> 5;
    const int lane = tid & 31;
    const int kg   = w >> 1;
    const int bh   = w & 1;
    const int bg   = lane >> 2;
    const int cg   = lane & 3;
    const int hc0  = blockIdx.x * HC;

    // ---- epilogue-role state (tid < 256) ----
    const int b  = tid & 63;
    const int cl = tid >> 6;
    float c_reg = 0.0f, h_reg = 0.0f;
    int nw_b = 0;
    float biasr[4] = {0.f, 0.f, 0.f, 0.f};
    if (tid < 256) {
        nw_b = num_words[b];
#pragma unroll
        for (int g = 0; g < 4; ++g) biasr[g] = bias[g * H_DIM + hc0 + cl];
    }

    const int actoff = bh * 32 + bg * 4;   // float offset inside a k-row of acts
    // lane's weight pointers (advance by WK_STRIDE float2 per k)
    const float2* wx0 = &g_Wdup[kg * XK_PER][blockIdx.x][cg * 4];
    const float2* wh0 = &g_Wdup[D_EMB + kg * HK_PER][blockIdx.x][cg * 4];

    u64 acc[2][4];

    // ---- prologue: x-part for t = 0 ----
    {
#pragma unroll
        for (int i = 0; i < 2; ++i)
#pragma unroll
            for (int j = 0; j < 4; ++j) acc[i][j] = 0ull;
        const float*  ap = g_XT + (kg * XK_PER) * B_SZ + actoff;
        const float2* wp = wx0;
#pragma unroll 8
        for (int kk = 0; kk < XK_PER; ++kk) {
            KBODY(ap, wp);
            ap += B_SZ; wp += WK_STRIDE;
        }
    }

    for (int t = 0; t < T_LEN; ++t) {
        if (t > 0) {
            // ---- wait for h(t), then accumulate h-part ----
            if (tid == 0) {
                while (*(volatile unsigned*)&g_bar_gen < (unsigned)t) { __nanosleep(32); }
                __threadfence();
            }
            __syncthreads();
            const float*  ap = g_hbuf[t & 1] + (kg * HK_PER) * B_SZ + actoff;
            const float2* wp = wh0;
#pragma unroll 8
            for (int kk = 0; kk < HK_PER; ++kk) {
                KBODY(ap, wp);
                ap += B_SZ; wp += WK_STRIDE;
            }
        }

        // ---- dump partials: red[w][e][lane], conflict-free STS.32 ----
        {
            float* base = red + (w * 16) * 32 + lane;
#pragma unroll
            for (int i = 0; i < 2; ++i)
#pragma unroll
                for (int j = 0; j < 4; ++j) {
                    float2 f = *(float2*)&acc[i][j];
                    int e = (i * 4 + j) * 2;
                    base[e * 32]       = f.x;
                    base[(e + 1) * 32] = f.y;
                }
        }
        __syncthreads();

        // ---- reduce over 8 k-groups + activations + state update ----
        if (tid < 256) {
            const int lane_r = (((b >> 2) & 7) << 2);
            const int e_r    = ((((b >> 1) & 1) * 4 + cl) << 1) | (b & 1);
            const int base_r = (b >> 5) * 512 + e_r * 32 + lane_r;
            float g4[4];
#pragma unroll
            for (int g = 0; g < 4; ++g) {
                float s = biasr[g];
                int idx = base_r + g;
#pragma unroll
                for (int kgi = 0; kgi < 8; ++kgi)
                    s += red[idx + kgi * 1024];          // w stride = 2*16*32
                g4[g] = s;
            }
            float ig = sigf(g4[0]);
            float jt = tanhf(g4[1]);
            float fg = sigf(g4[2] + 1.0f);
            float og = sigf(g4[3]);
            float cn = fg * c_reg + ig * jt;
            float hn = og * tanhf(cn);
            if (t < nw_b) { c_reg = cn; h_reg = hn; }
            g_hbuf[(t + 1) & 1][(hc0 + cl) * B_SZ + b] = h_reg;
        }
        __syncthreads();   // h CTA-visible; red reads done before next dump

        // ---- arrive (non-blocking), then overlap x-part of t+1 ----
        if (tid == 0) {
            __threadfence();
            unsigned tkt = atomicAdd(&g_bar_count, 1u);
            if (tkt == NCTA - 1) {
                atomicExch(&g_bar_count, 0u);
                __threadfence();
                atomicAdd(&g_bar_gen, 1u);   // gen = t+1
            }
        }
        if (t + 1 < T_LEN) {
#pragma unroll
            for (int i = 0; i < 2; ++i)
#pragma unroll
                for (int j = 0; j < 4; ++j) acc[i][j] = 0ull;
            const float*  ap = g_XT + (size_t)(t + 1) * (D_EMB * B_SZ)
                               + (kg * XK_PER) * B_SZ + actoff;
            const float2* wp = wx0;
#pragma unroll 8
            for (int kk = 0; kk < XK_PER; ++kk) {
                KBODY(ap, wp);
                ap += B_SZ; wp += WK_STRIDE;
            }
        }
    }

    // ---- final output [2, B, H] ----
    if (tid < 256) {
        out[(size_t)b * H_DIM + hc0 + cl]                = c_reg;
        out[(size_t)B_SZ * H_DIM + b * H_DIM + hc0 + cl] = h_reg;
    }
}

// ============================================================================
extern "C" void kernel_launch(void* const* d_in, const int* in_sizes, int n_in,
                              void* d_out, int out_size) {
    const int*   wi   = (const int*)d_in[0];
    const int*   nw   = (const int*)d_in[1];
    const float* emb  = (const float*)d_in[2];
    const float* kern = (const float*)d_in[3];
    const float* bias = (const float*)d_in[4];
    float* out = (float*)d_out;

    // maximize L1D: smem need is only 32KB static
    cudaFuncSetAttribute(lstm_persistent_kernel,
                         cudaFuncAttributePreferredSharedMemoryCarveout, 25);

    gather_transpose_kernel<<<T_LEN, 256>>>(wi, emb);
    pack_weights_kernel<<<KTOT, 256>>>(kern);
    lstm_persistent_kernel<<<NCTA, NTHR>>>(bias, nw, out);
}

// round 15
// speedup vs baseline: 1.3352x; 1.3352x over previous
#include <cuda_runtime.h>
#include <cuda_bf16.h>
#include <math.h>

// Problem constants
#define VOCAB 50000
#define D_EMB 256
#define H_DIM 512
#define B_SZ  64
#define T_LEN 512
#define KTOT  (D_EMB + H_DIM)   // 768
#define G4H   (4 * H_DIM)       // 2048

// k-pair decomposition: f32x2 lanes = (even k, odd k)
#define KP_TOT (KTOT / 2)       // 384 k-pairs
#define XKP    (D_EMB / 2)      // 128 x k-pairs
#define HKP    (H_DIM / 2)      // 256 h k-pairs

// Persistent-kernel config
#define NCTA 128                // CTA owns 4 h-cols -> 16 gate cols
#define NTHR 512                // 16 warps = 8 k-groups x 2 batch-halves
#define HC   4
#define XKP_W (XKP / 8)         // 16 x k-pairs per k-group
#define HKP_W (HKP / 8)         // 32 h k-pairs per k-group

// act row = 128 floats: [b][parity] interleaved
#define AROW 128
// weight row per kpair per CTA = 16 float2 = 128B (one cache line)
#define WROW 16

#define RED_F (16 * 16 * 32)    // red[w][e][lane] = 32KB

typedef unsigned long long u64;

// -------- device scratch --------
__device__ float    g_XT[T_LEN * XKP * AROW];     // [t][kp][b*2+par]
__device__ float    g_hp[2][HKP * AROW];          // [kp][b*2+par] double buffer
__device__ float2   g_Wp[KP_TOT][NCTA][WROW];     // {w_2kp, w_2kp+1} per col
__device__ unsigned g_bar_count;
__device__ unsigned g_bar_gen;

__device__ __forceinline__ u64 fma2(u64 a, u64 b, u64 c) {
    u64 d; asm("fma.rn.f32x2 %0, %1, %2, %3;" : "=l"(d) : "l"(a), "l"(b), "l"(c)); return d;
}
__device__ __forceinline__ float sigf(float x) { return 1.0f / (1.0f + __expf(-x)); }

// ============================================================================
// Kernel 1a: embedding gather -> k-pair-interleaved transpose; zero h0; bar reset.
// ============================================================================
__global__ void gather_transpose_kernel(const int* __restrict__ wi,
                                        const float* __restrict__ emb) {
    int t   = blockIdx.x;
    int tid = threadIdx.x;
    int b   = tid & 63;
    int q   = tid >> 6;

    int row = wi[b * T_LEN + t];
    const float* er = emb + (size_t)row * D_EMB + q * 64;
    float* xo = g_XT + (size_t)t * (XKP * AROW);

#pragma unroll
    for (int i = 0; i < 64; i += 4) {
        float4 v = __ldg((const float4*)(er + i));
        int d = q * 64 + i;      // even k
        *(float2*)&xo[(d >> 1) * AROW + b * 2]       = make_float2(v.x, v.y);
        *(float2*)&xo[((d >> 1) + 1) * AROW + b * 2] = make_float2(v.z, v.w);
    }
    // zero h buffer 0 (32768 floats): blocks 0..127 x 256 threads
    if (t < 128) g_hp[0][t * 256 + tid] = 0.0f;
    if (t == 0 && tid == 0) { g_bar_gen = 0; g_bar_count = 0; }
}

// ============================================================================
// Kernel 1b: pack weights as k-pairs, per-CTA contiguous 128B lines.
// g_Wp[kp][cta][c] = { kern[2kp][col], kern[2kp+1][col] },
//   col = (c>>2)*H_DIM + cta*4 + (c&3)   (c = gate*4 + local h col)
// ============================================================================
__global__ void pack_weights_kernel(const float* __restrict__ kern) {
    int kp  = blockIdx.x;        // 0..383
    int tid = threadIdx.x;       // 256
    const float* r0 = kern + (size_t)(2 * kp) * G4H;
    const float* r1 = r0 + G4H;
    for (int e = tid; e < NCTA * WROW; e += 256) {
        int cta = e >> 4, c = e & 15;
        int col = (c >> 2) * H_DIM + cta * 4 + (c & 3);
        g_Wp[kp][cta][c] = make_float2(r0[col], r1[col]);
    }
}

// ============================================================================
// Kernel 2: persistent LSTM, 128 CTAs x 512 threads.
//  - warp w = (kg = w>>1, bh = w&1): k-pair octant, batch-half
//  - lane (bg = lane>>2, cg = lane&3): 4 batches (i) x 4 cols (j), acc[4][4]
//  - f32x2 lanes = (k even, k odd): acts AND weights both natural pairs,
//    zero broadcast cost; fold parity with FADD at dump
//  - acts:    __ldcg (L2), weights: plain LDG (L1-resident, 48KB/CTA)
//  - x-GEMM for step t+1 overlapped with the grid barrier wait
// ============================================================================

// per k-pair: 4x LDG.128 + 16 FFMA2 (covers 2 k's)
#define KPBODY(AP, WP)                                              \
    {                                                               \
        const ulonglong2* _a = (const ulonglong2*)(AP);             \
        const ulonglong2* _w = (const ulonglong2*)(WP);             \
        ulonglong2 va0 = __ldcg(_a);                                \
        ulonglong2 va1 = __ldcg(_a + 1);                            \
        ulonglong2 wv0 = _w[0];                                     \
        ulonglong2 wv1 = _w[1];                                     \
        acc[0][0] = fma2(va0.x, wv0.x, acc[0][0]);                  \
        acc[0][1] = fma2(va0.x, wv0.y, acc[0][1]);                  \
        acc[0][2] = fma2(va0.x, wv1.x, acc[0][2]);                  \
        acc[0][3] = fma2(va0.x, wv1.y, acc[0][3]);                  \
        acc[1][0] = fma2(va0.y, wv0.x, acc[1][0]);                  \
        acc[1][1] = fma2(va0.y, wv0.y, acc[1][1]);                  \
        acc[1][2] = fma2(va0.y, wv1.x, acc[1][2]);                  \
        acc[1][3] = fma2(va0.y, wv1.y, acc[1][3]);                  \
        acc[2][0] = fma2(va1.x, wv0.x, acc[2][0]);                  \
        acc[2][1] = fma2(va1.x, wv0.y, acc[2][1]);                  \
        acc[2][2] = fma2(va1.x, wv1.x, acc[2][2]);                  \
        acc[2][3] = fma2(va1.x, wv1.y, acc[2][3]);                  \
        acc[3][0] = fma2(va1.y, wv0.x, acc[3][0]);                  \
        acc[3][1] = fma2(va1.y, wv0.y, acc[3][1]);                  \
        acc[3][2] = fma2(va1.y, wv1.x, acc[3][2]);                  \
        acc[3][3] = fma2(va1.y, wv1.y, acc[3][3]);                  \
    }

#define WKP_STRIDE (NCTA * WROW)    // float2 per k-pair row

__global__ void __launch_bounds__(NTHR, 1)
lstm_persistent_kernel(const float* __restrict__ bias,
                       const int*   __restrict__ num_words,
                       float*       __restrict__ out) {
    __shared__ float red[RED_F];    // [w][e=i*4+j][lane]

    const int tid  = threadIdx.x;
    const int w    = tid >> 5;
    const int lane = tid & 31;
    const int kg   = w >> 1;
    const int bh   = w & 1;
    const int bg   = lane >> 2;
    const int cg   = lane & 3;
    const int hc0  = blockIdx.x * HC;

    // ---- epilogue-role state (tid < 256) ----
    const int b  = tid & 63;
    const int cl = tid >> 6;
    float c_reg = 0.0f, h_reg = 0.0f;
    int nw_b = 0;
    float biasr[4] = {0.f, 0.f, 0.f, 0.f};
    if (tid < 256) {
        nw_b = num_words[b];
#pragma unroll
        for (int g = 0; g < 4; ++g) biasr[g] = bias[g * H_DIM + hc0 + cl];
    }

    const int actoff = bh * 64 + bg * 8;                       // floats into AROW
    const float2* wx0 = &g_Wp[kg * XKP_W][blockIdx.x][cg * 4];
    const float2* wh0 = &g_Wp[XKP + kg * HKP_W][blockIdx.x][cg * 4];

    u64 acc[4][4];

    // ---- prologue: x-part for t = 0 ----
    {
#pragma unroll
        for (int i = 0; i < 4; ++i)
#pragma unroll
            for (int j = 0; j < 4; ++j) acc[i][j] = 0ull;
        const float*  ap = g_XT + (kg * XKP_W) * AROW + actoff;
        const float2* wp = wx0;
#pragma unroll 4
        for (int kk = 0; kk < XKP_W; ++kk) {
            KPBODY(ap, wp);
            ap += AROW; wp += WKP_STRIDE;
        }
    }

    for (int t = 0; t < T_LEN; ++t) {
        if (t > 0) {
            // ---- wait for h(t), then accumulate h-part ----
            if (tid == 0) {
                while (*(volatile unsigned*)&g_bar_gen < (unsigned)t) { __nanosleep(32); }
                __threadfence();
            }
            __syncthreads();
            const float*  ap = g_hp[t & 1] + (kg * HKP_W) * AROW + actoff;
            const float2* wp = wh0;
#pragma unroll 4
            for (int kk = 0; kk < HKP_W; ++kk) {
                KPBODY(ap, wp);
                ap += AROW; wp += WKP_STRIDE;
            }
        }

        // ---- fold k-parity (FADD) + dump: red[w][i*4+j][lane], conflict-free ----
        {
            float* base = red + w * (16 * 32) + lane;
#pragma unroll
            for (int i = 0; i < 4; ++i)
#pragma unroll
                for (int j = 0; j < 4; ++j) {
                    float2 f = *(float2*)&acc[i][j];
                    base[(i * 4 + j) * 32] = f.x + f.y;
                }
        }
        __syncthreads();

        // ---- reduce over 8 k-groups + activations + state update ----
        if (tid < 256) {
            const int bhh = b >> 5;
            const int bgg = (b >> 2) & 7;
            const int ii  = b & 3;
            // value for (b, col=cl, gate g) lives at red[kg*2+bhh][ii*4+cl][bgg*4+cg=g]
            const float* rp = red + bhh * (16 * 32) + (ii * 4 + cl) * 32 + bgg * 4;
            float g4[4] = {biasr[0], biasr[1], biasr[2], biasr[3]};
#pragma unroll
            for (int kgi = 0; kgi < 8; ++kgi) {
                float4 v = *(const float4*)(rp + kgi * (2 * 16 * 32));
                g4[0] += v.x; g4[1] += v.y; g4[2] += v.z; g4[3] += v.w;
            }
            float ig = sigf(g4[0]);
            float jt = tanhf(g4[1]);
            float fg = sigf(g4[2] + 1.0f);
            float og = sigf(g4[3]);
            float cn = fg * c_reg + ig * jt;
            float hn = og * tanhf(cn);
            if (t < nw_b) { c_reg = cn; h_reg = hn; }
            // paired h store: g_hp[buf][ (hcol>>1)*AROW + b*2 + (hcol&1) ]
            int hcol = hc0 + cl;
            g_hp[(t + 1) & 1][(hcol >> 1) * AROW + b * 2 + (hcol & 1)] = h_reg;
        }
        __syncthreads();   // h CTA-visible; red reads done before next dump

        // ---- arrive (non-blocking), then overlap x-part of t+1 ----
        if (tid == 0) {
            __threadfence();
            unsigned tkt = atomicAdd(&g_bar_count, 1u);
            if (tkt == NCTA - 1) {
                atomicExch(&g_bar_count, 0u);
                __threadfence();
                atomicAdd(&g_bar_gen, 1u);   // gen = t+1
            }
        }
        if (t + 1 < T_LEN) {
#pragma unroll
            for (int i = 0; i < 4; ++i)
#pragma unroll
                for (int j = 0; j < 4; ++j) acc[i][j] = 0ull;
            const float*  ap = g_XT + (size_t)(t + 1) * (XKP * AROW)
                               + (kg * XKP_W) * AROW + actoff;
            const float2* wp = wx0;
#pragma unroll 4
            for (int kk = 0; kk < XKP_W; ++kk) {
                KPBODY(ap, wp);
                ap += AROW; wp += WKP_STRIDE;
            }
        }
    }

    // ---- final output [2, B, H] ----
    if (tid < 256) {
        out[(size_t)b * H_DIM + hc0 + cl]                = c_reg;
        out[(size_t)B_SZ * H_DIM + b * H_DIM + hc0 + cl] = h_reg;
    }
}

// ============================================================================
extern "C" void kernel_launch(void* const* d_in, const int* in_sizes, int n_in,
                              void* d_out, int out_size) {
    const int*   wi   = (const int*)d_in[0];
    const int*   nw   = (const int*)d_in[1];
    const float* emb  = (const float*)d_in[2];
    const float* kern = (const float*)d_in[3];
    const float* bias = (const float*)d_in[4];
    float* out = (float*)d_out;

    // smem need is only 32KB static -> keep L1D large for the 48KB weight slice
    cudaFuncSetAttribute(lstm_persistent_kernel,
                         cudaFuncAttributePreferredSharedMemoryCarveout, 25);

    gather_transpose_kernel<<<T_LEN, 256>>>(wi, emb);
    pack_weights_kernel<<<KP_TOT, 256>>>(kern);
    lstm_persistent_kernel<<<NCTA, NTHR>>>(bias, nw, out);
}